// round 15
// baseline (speedup 1.0000x reference)
#include <cuda_runtime.h>
#include <cuda_bf16.h>

// ---------------------------------------------------------------------------
// VQC: 4 qubits, 3 layers, BATCH=524288. SINGLE fused persistent kernel.
// z_w(x) = exact 81-term polynomial in {1, cos x_q, sin x_q}^{⊗4};
// coefficients T depend only on weights.
//  Phase A (shuffle builder, no syncthreads — R12-verified): 8 warps, each
//    lane owns one amplitude of one U column; CNOT = shfl gather, RY =
//    shfl.bfly + 4 FMA, RZ diagonal (last-layer RZ cancels in U^H S U).
//  Phase M/T (R12-verified): M_w = Re(U^† S_w U) -> T[81] float4, in smem.
//  Phase B (R13-verified Horner, EPT=2): grid-stride tiles of 512,
//    z = Σ_i0 v0 Σ_i1 v1 Σ_i2 v2 Σ_i3 T v3, packed fma.rn.f32x2 lanes
//    = (w0,w1)/(w2,w3). Persistent grid 342 = one wave, builder runs once
//    per resident CTA; no second kernel, no PDL wait, no launch gap.
// ---------------------------------------------------------------------------

#define DIM 16
#define TPB 256
#define EPT 2
#define TILE (TPB * EPT)   // 512
#define GRID 342           // ceil(1024 tiles / 3 per CTA); single wave

// ---------------- packed f32x2 helpers (PTX-only on Blackwell) -------------
__device__ __forceinline__ unsigned long long pack2(float lo, float hi) {
    unsigned long long r;
    asm("mov.b64 %0, {%1, %2};" : "=l"(r) : "f"(lo), "f"(hi));
    return r;
}
__device__ __forceinline__ void unpack2(unsigned long long v, float& lo, float& hi) {
    asm("mov.b64 {%0, %1}, %2;" : "=f"(lo), "=f"(hi) : "l"(v));
}
__device__ __forceinline__ unsigned long long fma2(unsigned long long a,
                                                   unsigned long long b,
                                                   unsigned long long c) {
    unsigned long long d;
    asm("fma.rn.f32x2 %0, %1, %2, %3;" : "=l"(d) : "l"(a), "l"(b), "l"(c));
    return d;
}

// CNOT ring permutation for one layer (gather index).
__device__ __forceinline__ int cnot_q(int idx) {
    int q = idx;
#pragma unroll
    for (int i = 3; i >= 0; --i)
        q = q ^ ((((q >> (3 - i)) & 1)) << (3 - ((i + 1) & 3)));
    return q;
}

__global__ __launch_bounds__(TPB, 3)
void vqc_fused(const float* __restrict__ x, const float* __restrict__ w,
               float* __restrict__ out, int B, int numTiles) {
    __shared__ float2 sU[DIM * 17];   // sU[col*17 + amp]
    __shared__ float4 sM[256];
    __shared__ float4 sT[81];

    const int t = threadIdx.x;
    const int lane = t & 31;
    const int wi = t >> 5;
    const unsigned FULL = 0xffffffffu;

    // ---- Phase A: shuffle-circuit U builder (no __syncthreads inside) -----
    {
        float my_cy, my_sy, my_cz, my_sz;
        const float wy = (lane < 12) ? w[lane * 2 + 0] : 0.f;
        const float wz = (lane < 12) ? w[lane * 2 + 1] : 0.f;
        __sincosf(0.5f * wy, &my_sy, &my_cy);
        __sincosf(0.5f * wz, &my_sz, &my_cz);

        const int amp = lane & 15;
        const int col = (wi << 1) | (lane >> 4);   // warp wi owns cols 2wi, 2wi+1
        float re = (amp == col) ? 1.f : 0.f;
        float im = 0.f;

#pragma unroll
        for (int layer = 0; layer < 3; ++layer) {
            {   // CNOT ring: new[amp] = old[Q(amp)] (gather within 16-lane half)
                const int srcLane = (lane & 16) | cnot_q(amp);
                const float nre = __shfl_sync(FULL, re, srcLane);
                const float nim = __shfl_sync(FULL, im, srcLane);
                re = nre; im = nim;
            }
#pragma unroll
            for (int g = 0; g < 4; ++g) {
                const int gidx = layer * 4 + g;
                const float cy = __shfl_sync(FULL, my_cy, gidx);
                const float sy = __shfl_sync(FULL, my_sy, gidx);
                const int bit = 3 - g, mask = 1 << bit;
                const float pre = __shfl_xor_sync(FULL, re, mask);
                const float pim = __shfl_xor_sync(FULL, im, mask);
                float br, bi;
                if (amp & mask) { br = sy * pre + cy * re; bi = sy * pim + cy * im; }
                else            { br = cy * re - sy * pre; bi = cy * im - sy * pim; }
                re = br; im = bi;
                if (layer != 2) {   // RZ (last layer's RZ cancels in U^H S U)
                    const float cz = __shfl_sync(FULL, my_cz, gidx);
                    const float sz = __shfl_sync(FULL, my_sz, gidx);
                    if (amp & mask) { const float o = cz * br - sz * bi;
                                      im = cz * bi + sz * br; re = o; }
                    else            { const float o = cz * br + sz * bi;
                                      im = cz * bi - sz * br; re = o; }
                }
            }
        }
        sU[col * 17 + amp] = make_float2(re, im);
    }
    __syncthreads();

    // ---- Phase M: M_w[j,j'] = sum_k s_wk (Ur Ur' + Ui Ui') ----------------
    {
        const int j = t >> 4, jp = t & 15;
        float m0 = 0.f, m1 = 0.f, m2 = 0.f, m3 = 0.f;
#pragma unroll
        for (int k = 0; k < DIM; ++k) {
            const float2 a = sU[j * 17 + k];
            const float2 b = sU[jp * 17 + k];
            const float pr = a.x * b.x + a.y * b.y;
            if (k & 8) m0 -= pr; else m0 += pr;
            if (k & 4) m1 -= pr; else m1 += pr;
            if (k & 2) m2 -= pr; else m2 += pr;
            if (k & 1) m3 -= pr; else m3 += pr;
        }
        sM[t] = make_float4(m0, m1, m2, m3);
    }
    __syncthreads();

    // ---- Phase T: 81 monomial coefficients, straight into smem ------------
    if (t < 81) {
        const int i0 = t / 27, i1 = (t / 9) % 3, i2 = (t / 3) % 3, i3 = t % 3;
        const int M1 = ((i0 == 1) << 3) | ((i1 == 1) << 2) | ((i2 == 1) << 1) | (i3 == 1);
        const int M2 = ((i0 == 2) << 3) | ((i1 == 2) << 2) | ((i2 == 2) << 1) | (i3 == 2);
        float a0 = 0.f, a1 = 0.f, a2 = 0.f, a3 = 0.f;
#pragma unroll
        for (int b = 0; b < 16; ++b) {
            const float4 mm = sM[b * 16 + (b ^ M2)];
            const float sg = (__popc(b & M1) & 1) ? -1.f : 1.f;
            a0 += sg * mm.x; a1 += sg * mm.y; a2 += sg * mm.z; a3 += sg * mm.w;
        }
        const float s = 0.0625f;
        sT[t] = make_float4(a0 * s, a1 * s, a2 * s, a3 * s);
    }
    __syncthreads();

    // ---- Phase B: persistent grid-stride Horner evaluation ----------------
    const ulonglong2* cT = reinterpret_cast<const ulonglong2*>(sT);

    for (int tile = blockIdx.x; tile < numTiles; tile += GRID) {
        const int base = tile * TILE + t;

        bool valid[EPT];
        unsigned long long c0d[EPT], s0d[EPT], c1d[EPT], s1d[EPT];
        unsigned long long c2d[EPT], s2d[EPT], c3d[EPT], s3d[EPT];
#pragma unroll
        for (int e = 0; e < EPT; ++e) {
            const int b = base + e * TPB;
            valid[e] = (b < B);
            const float4 xv = valid[e] ? reinterpret_cast<const float4*>(x)[b]
                                       : make_float4(0.f, 0.f, 0.f, 0.f);
            float c0, s0, c1, s1, c2, s2, c3, s3;
            __sincosf(xv.x, &s0, &c0);   // full angle (double-angle folded into T)
            __sincosf(xv.y, &s1, &c1);
            __sincosf(xv.z, &s2, &c2);
            __sincosf(xv.w, &s3, &c3);
            c0d[e] = pack2(c0, c0); s0d[e] = pack2(s0, s0);
            c1d[e] = pack2(c1, c1); s1d[e] = pack2(s1, s1);
            c2d[e] = pack2(c2, c2); s2d[e] = pack2(s2, s2);
            c3d[e] = pack2(c3, c3); s3d[e] = pack2(s3, s3);
        }

        unsigned long long z01[EPT], z23[EPT];
        unsigned long long Q01[EPT], Q23[EPT];

#pragma unroll
        for (int i0 = 0; i0 < 3; ++i0) {
#pragma unroll
            for (int i1 = 0; i1 < 3; ++i1) {
                const int gi = i0 * 3 + i1;
                ulonglong2 c[9];
#pragma unroll
                for (int k = 0; k < 9; ++k) c[k] = cT[gi * 9 + k];

#pragma unroll
                for (int e = 0; e < EPT; ++e) {
                    const unsigned long long u0a =
                        fma2(c[2].x, s3d[e], fma2(c[1].x, c3d[e], c[0].x));
                    const unsigned long long u1a =
                        fma2(c[5].x, s3d[e], fma2(c[4].x, c3d[e], c[3].x));
                    const unsigned long long u2a =
                        fma2(c[8].x, s3d[e], fma2(c[7].x, c3d[e], c[6].x));
                    const unsigned long long in01 =
                        fma2(u2a, s2d[e], fma2(u1a, c2d[e], u0a));
                    const unsigned long long u0b =
                        fma2(c[2].y, s3d[e], fma2(c[1].y, c3d[e], c[0].y));
                    const unsigned long long u1b =
                        fma2(c[5].y, s3d[e], fma2(c[4].y, c3d[e], c[3].y));
                    const unsigned long long u2b =
                        fma2(c[8].y, s3d[e], fma2(c[7].y, c3d[e], c[6].y));
                    const unsigned long long in23 =
                        fma2(u2b, s2d[e], fma2(u1b, c2d[e], u0b));

                    if (i1 == 0)      { Q01[e] = in01;                       Q23[e] = in23; }
                    else if (i1 == 1) { Q01[e] = fma2(c1d[e], in01, Q01[e]); Q23[e] = fma2(c1d[e], in23, Q23[e]); }
                    else              { Q01[e] = fma2(s1d[e], in01, Q01[e]); Q23[e] = fma2(s1d[e], in23, Q23[e]); }
                }
            }
#pragma unroll
            for (int e = 0; e < EPT; ++e) {
                if (i0 == 0)      { z01[e] = Q01[e];                       z23[e] = Q23[e]; }
                else if (i0 == 1) { z01[e] = fma2(c0d[e], Q01[e], z01[e]); z23[e] = fma2(c0d[e], Q23[e], z23[e]); }
                else              { z01[e] = fma2(s0d[e], Q01[e], z01[e]); z23[e] = fma2(s0d[e], Q23[e], z23[e]); }
            }
        }

#pragma unroll
        for (int e = 0; e < EPT; ++e) {
            if (!valid[e]) continue;
            float z0, z1, z2, z3;
            unpack2(z01[e], z0, z1);
            unpack2(z23[e], z2, z3);
            reinterpret_cast<float4*>(out)[base + e * TPB] =
                make_float4(z0, z1, z2, z3);
        }
    }
}

// ---------------------------------------------------------------------------
extern "C" void kernel_launch(void* const* d_in, const int* in_sizes, int n_in,
                              void* d_out, int out_size) {
    int ix = 0, iw = 1;
    if (n_in >= 2 && in_sizes[0] <= in_sizes[1]) { ix = 1; iw = 0; }
    const float* x = (const float*)d_in[ix];
    const float* w = (const float*)d_in[iw];
    float* out = (float*)d_out;
    const int B = in_sizes[ix] / 4;

    const int numTiles = (B + TILE - 1) / TILE;   // 1024 for B=524288
    vqc_fused<<<GRID, TPB>>>(x, w, out, B, numTiles);
}

// round 16
// speedup vs baseline: 1.8617x; 1.8617x over previous
#include <cuda_runtime.h>
#include <cuda_bf16.h>

// ---------------------------------------------------------------------------
// VQC: 4 qubits, 3 layers, BATCH=524288. SINGLE fused persistent kernel.
// z_w(x) = exact 81-term polynomial in {1, cos x_q, sin x_q}^{⊗4};
// coefficients T depend only on weights.
//  Phase A: barrier-free shuffle builder (R12-verified lane math), 4 warps,
//    each lane carries TWO column-pairs; CNOT = shfl gather, RY = shfl.bfly,
//    RZ diagonal (last-layer RZ cancels in U^† S U).
//  Phase M/T (verified): M_w = Re(U^† S_w U) -> T[81] float4 in smem.
//  Phase B (R13-verified Horner, EPT=2, TPB=128): persistent grid-stride,
//    z = Σ_i0 v0 Σ_i1 v1 Σ_i2 v2 Σ_i3 T v3, fma.rn.f32x2 lanes=(w0,w1)/(w2,w3).
//  launch_bounds(128,5): cap 102 >> measured ~80-reg body — NO spill (R15 fix).
//  GRID=683: single wave at 5 CTAs/SM, exactly 3 tiles/CTA of 2048 tiles.
// ---------------------------------------------------------------------------

#define DIM 16
#define TPB 128
#define EPT 2
#define TILE (TPB * EPT)   // 256
#define GRID 683

// ---------------- packed f32x2 helpers (PTX-only on Blackwell) -------------
__device__ __forceinline__ unsigned long long pack2(float lo, float hi) {
    unsigned long long r;
    asm("mov.b64 %0, {%1, %2};" : "=l"(r) : "f"(lo), "f"(hi));
    return r;
}
__device__ __forceinline__ void unpack2(unsigned long long v, float& lo, float& hi) {
    asm("mov.b64 {%0, %1}, %2;" : "=f"(lo), "=f"(hi) : "l"(v));
}
__device__ __forceinline__ unsigned long long fma2(unsigned long long a,
                                                   unsigned long long b,
                                                   unsigned long long c) {
    unsigned long long d;
    asm("fma.rn.f32x2 %0, %1, %2, %3;" : "=l"(d) : "l"(a), "l"(b), "l"(c));
    return d;
}

// CNOT ring permutation for one layer (gather index).
__device__ __forceinline__ int cnot_q(int idx) {
    int q = idx;
#pragma unroll
    for (int i = 3; i >= 0; --i)
        q = q ^ ((((q >> (3 - i)) & 1)) << (3 - ((i + 1) & 3)));
    return q;
}

__global__ __launch_bounds__(TPB, 5)
void vqc_fused(const float* __restrict__ x, const float* __restrict__ w,
               float* __restrict__ out, int B, int numTiles) {
    __shared__ float2 sU[DIM * 17];   // sU[col*17 + amp]
    __shared__ float4 sM[256];
    __shared__ float4 sT[81];

    const int t = threadIdx.x;
    const int lane = t & 31;
    const int wi = t >> 5;            // 4 warps
    const unsigned FULL = 0xffffffffu;

    // ---- Phase A: shuffle-circuit U builder (no __syncthreads inside) -----
    {
        float my_cy, my_sy, my_cz, my_sz;
        const float wy = (lane < 12) ? w[lane * 2 + 0] : 0.f;
        const float wz = (lane < 12) ? w[lane * 2 + 1] : 0.f;
        __sincosf(0.5f * wy, &my_sy, &my_cy);
        __sincosf(0.5f * wz, &my_sz, &my_cz);

        const int amp = lane & 15;
        // lane carries two column-pairs: pair p -> column wi*4 + 2p + (lane>>4)
        float re[2], im[2];
        int colp[2];
#pragma unroll
        for (int p = 0; p < 2; ++p) {
            colp[p] = (wi << 2) + (p << 1) + (lane >> 4);
            re[p] = (amp == colp[p]) ? 1.f : 0.f;
            im[p] = 0.f;
        }

#pragma unroll
        for (int layer = 0; layer < 3; ++layer) {
            {   // CNOT ring: new[amp] = old[Q(amp)] (gather within 16-lane half)
                const int srcLane = (lane & 16) | cnot_q(amp);
#pragma unroll
                for (int p = 0; p < 2; ++p) {
                    const float nre = __shfl_sync(FULL, re[p], srcLane);
                    const float nim = __shfl_sync(FULL, im[p], srcLane);
                    re[p] = nre; im[p] = nim;
                }
            }
#pragma unroll
            for (int g = 0; g < 4; ++g) {
                const int gidx = layer * 4 + g;
                const float cy = __shfl_sync(FULL, my_cy, gidx);
                const float sy = __shfl_sync(FULL, my_sy, gidx);
                const float cz = __shfl_sync(FULL, my_cz, gidx);
                const float sz = __shfl_sync(FULL, my_sz, gidx);
                const int bit = 3 - g, mask = 1 << bit;
#pragma unroll
                for (int p = 0; p < 2; ++p) {
                    const float pre = __shfl_xor_sync(FULL, re[p], mask);
                    const float pim = __shfl_xor_sync(FULL, im[p], mask);
                    float br, bi;
                    if (amp & mask) { br = sy * pre + cy * re[p]; bi = sy * pim + cy * im[p]; }
                    else            { br = cy * re[p] - sy * pre; bi = cy * im[p] - sy * pim; }
                    re[p] = br; im[p] = bi;
                    if (layer != 2) {   // RZ (last layer's RZ cancels in U^H S U)
                        if (amp & mask) { const float o = cz * br - sz * bi;
                                          im[p] = cz * bi + sz * br; re[p] = o; }
                        else            { const float o = cz * br + sz * bi;
                                          im[p] = cz * bi - sz * br; re[p] = o; }
                    }
                }
            }
        }
#pragma unroll
        for (int p = 0; p < 2; ++p)
            sU[colp[p] * 17 + amp] = make_float2(re[p], im[p]);
    }
    __syncthreads();

    // ---- Phase M: M_w[j,j'] = sum_k s_wk (Ur Ur' + Ui Ui') ----------------
#pragma unroll
    for (int e = t; e < 256; e += TPB) {
        const int j = e >> 4, jp = e & 15;
        float m0 = 0.f, m1 = 0.f, m2 = 0.f, m3 = 0.f;
#pragma unroll
        for (int k = 0; k < DIM; ++k) {
            const float2 a = sU[j * 17 + k];
            const float2 b = sU[jp * 17 + k];
            const float pr = a.x * b.x + a.y * b.y;
            if (k & 8) m0 -= pr; else m0 += pr;
            if (k & 4) m1 -= pr; else m1 += pr;
            if (k & 2) m2 -= pr; else m2 += pr;
            if (k & 1) m3 -= pr; else m3 += pr;
        }
        sM[e] = make_float4(m0, m1, m2, m3);
    }
    __syncthreads();

    // ---- Phase T: 81 monomial coefficients, straight into smem ------------
    if (t < 81) {
        const int i0 = t / 27, i1 = (t / 9) % 3, i2 = (t / 3) % 3, i3 = t % 3;
        const int M1 = ((i0 == 1) << 3) | ((i1 == 1) << 2) | ((i2 == 1) << 1) | (i3 == 1);
        const int M2 = ((i0 == 2) << 3) | ((i1 == 2) << 2) | ((i2 == 2) << 1) | (i3 == 2);
        float a0 = 0.f, a1 = 0.f, a2 = 0.f, a3 = 0.f;
#pragma unroll
        for (int b = 0; b < 16; ++b) {
            const float4 mm = sM[b * 16 + (b ^ M2)];
            const float sg = (__popc(b & M1) & 1) ? -1.f : 1.f;
            a0 += sg * mm.x; a1 += sg * mm.y; a2 += sg * mm.z; a3 += sg * mm.w;
        }
        const float s = 0.0625f;
        sT[t] = make_float4(a0 * s, a1 * s, a2 * s, a3 * s);
    }
    __syncthreads();

    // ---- Phase B: persistent grid-stride Horner (R13-verified) ------------
    const ulonglong2* cT = reinterpret_cast<const ulonglong2*>(sT);

    for (int tile = blockIdx.x; tile < numTiles; tile += GRID) {
        const int base = tile * TILE + t;

        bool valid[EPT];
        unsigned long long c0d[EPT], s0d[EPT], c1d[EPT], s1d[EPT];
        unsigned long long c2d[EPT], s2d[EPT], c3d[EPT], s3d[EPT];
#pragma unroll
        for (int e = 0; e < EPT; ++e) {
            const int b = base + e * TPB;
            valid[e] = (b < B);
            const float4 xv = valid[e] ? reinterpret_cast<const float4*>(x)[b]
                                       : make_float4(0.f, 0.f, 0.f, 0.f);
            float c0, s0, c1, s1, c2, s2, c3, s3;
            __sincosf(xv.x, &s0, &c0);   // full angle (double-angle folded into T)
            __sincosf(xv.y, &s1, &c1);
            __sincosf(xv.z, &s2, &c2);
            __sincosf(xv.w, &s3, &c3);
            c0d[e] = pack2(c0, c0); s0d[e] = pack2(s0, s0);
            c1d[e] = pack2(c1, c1); s1d[e] = pack2(s1, s1);
            c2d[e] = pack2(c2, c2); s2d[e] = pack2(s2, s2);
            c3d[e] = pack2(c3, c3); s3d[e] = pack2(s3, s3);
        }

        unsigned long long z01[EPT], z23[EPT];
        unsigned long long Q01[EPT], Q23[EPT];

#pragma unroll
        for (int i0 = 0; i0 < 3; ++i0) {
#pragma unroll
            for (int i1 = 0; i1 < 3; ++i1) {
                const int gi = i0 * 3 + i1;
                ulonglong2 c[9];
#pragma unroll
                for (int k = 0; k < 9; ++k) c[k] = cT[gi * 9 + k];

#pragma unroll
                for (int e = 0; e < EPT; ++e) {
                    const unsigned long long u0a =
                        fma2(c[2].x, s3d[e], fma2(c[1].x, c3d[e], c[0].x));
                    const unsigned long long u1a =
                        fma2(c[5].x, s3d[e], fma2(c[4].x, c3d[e], c[3].x));
                    const unsigned long long u2a =
                        fma2(c[8].x, s3d[e], fma2(c[7].x, c3d[e], c[6].x));
                    const unsigned long long in01 =
                        fma2(u2a, s2d[e], fma2(u1a, c2d[e], u0a));
                    const unsigned long long u0b =
                        fma2(c[2].y, s3d[e], fma2(c[1].y, c3d[e], c[0].y));
                    const unsigned long long u1b =
                        fma2(c[5].y, s3d[e], fma2(c[4].y, c3d[e], c[3].y));
                    const unsigned long long u2b =
                        fma2(c[8].y, s3d[e], fma2(c[7].y, c3d[e], c[6].y));
                    const unsigned long long in23 =
                        fma2(u2b, s2d[e], fma2(u1b, c2d[e], u0b));

                    if (i1 == 0)      { Q01[e] = in01;                       Q23[e] = in23; }
                    else if (i1 == 1) { Q01[e] = fma2(c1d[e], in01, Q01[e]); Q23[e] = fma2(c1d[e], in23, Q23[e]); }
                    else              { Q01[e] = fma2(s1d[e], in01, Q01[e]); Q23[e] = fma2(s1d[e], in23, Q23[e]); }
                }
            }
#pragma unroll
            for (int e = 0; e < EPT; ++e) {
                if (i0 == 0)      { z01[e] = Q01[e];                       z23[e] = Q23[e]; }
                else if (i0 == 1) { z01[e] = fma2(c0d[e], Q01[e], z01[e]); z23[e] = fma2(c0d[e], Q23[e], z23[e]); }
                else              { z01[e] = fma2(s0d[e], Q01[e], z01[e]); z23[e] = fma2(s0d[e], Q23[e], z23[e]); }
            }
        }

#pragma unroll
        for (int e = 0; e < EPT; ++e) {
            if (!valid[e]) continue;
            float z0, z1, z2, z3;
            unpack2(z01[e], z0, z1);
            unpack2(z23[e], z2, z3);
            reinterpret_cast<float4*>(out)[base + e * TPB] =
                make_float4(z0, z1, z2, z3);
        }
    }
}

// ---------------------------------------------------------------------------
extern "C" void kernel_launch(void* const* d_in, const int* in_sizes, int n_in,
                              void* d_out, int out_size) {
    int ix = 0, iw = 1;
    if (n_in >= 2 && in_sizes[0] <= in_sizes[1]) { ix = 1; iw = 0; }
    const float* x = (const float*)d_in[ix];
    const float* w = (const float*)d_in[iw];
    float* out = (float*)d_out;
    const int B = in_sizes[ix] / 4;

    const int numTiles = (B + TILE - 1) / TILE;   // 2048 for B=524288
    const int grid = numTiles < GRID ? numTiles : GRID;
    vqc_fused<<<grid, TPB>>>(x, w, out, B, numTiles);
}

// round 17
// speedup vs baseline: 2.8314x; 1.5209x over previous
#include <cuda_runtime.h>
#include <cuda_bf16.h>

// ---------------------------------------------------------------------------
// VQC: 4 qubits, 3 layers, BATCH=524288. SINGLE fused kernel, NON-persistent
// (one tile per block — the persistent grid-stride loop demotes the EPT
// register arrays to local memory; R15/R16's L2 blowup).
// z_w(x) = exact 81-term polynomial in {1, cos x_q, sin x_q}^{⊗4}.
//  Phase A (R16-verified): barrier-free shuffle builder, 4 warps, each lane
//    carries two column-pairs; CNOT = shfl gather, RY = shfl.bfly, RZ diag
//    (last-layer RZ cancels in U^† S U).
//  Phase M/T (verified): M_w = Re(U^† S_w U) -> T[81] float4 in smem.
//  Phase B (R13-verified): three-level Horner, EPT=2, fma.rn.f32x2 lanes =
//    (w0,w1)/(w2,w3), 9 coeffs batch-loaded per group.
// ---------------------------------------------------------------------------

#define DIM 16
#define TPB 128
#define EPT 2
#define TILE (TPB * EPT)   // 256

// ---------------- packed f32x2 helpers (PTX-only on Blackwell) -------------
__device__ __forceinline__ unsigned long long pack2(float lo, float hi) {
    unsigned long long r;
    asm("mov.b64 %0, {%1, %2};" : "=l"(r) : "f"(lo), "f"(hi));
    return r;
}
__device__ __forceinline__ void unpack2(unsigned long long v, float& lo, float& hi) {
    asm("mov.b64 {%0, %1}, %2;" : "=f"(lo), "=f"(hi) : "l"(v));
}
__device__ __forceinline__ unsigned long long fma2(unsigned long long a,
                                                   unsigned long long b,
                                                   unsigned long long c) {
    unsigned long long d;
    asm("fma.rn.f32x2 %0, %1, %2, %3;" : "=l"(d) : "l"(a), "l"(b), "l"(c));
    return d;
}

// CNOT ring permutation for one layer (gather index).
__device__ __forceinline__ int cnot_q(int idx) {
    int q = idx;
#pragma unroll
    for (int i = 3; i >= 0; --i)
        q = q ^ ((((q >> (3 - i)) & 1)) << (3 - ((i + 1) & 3)));
    return q;
}

__global__ __launch_bounds__(TPB, 6)
void vqc_fused(const float* __restrict__ x, const float* __restrict__ w,
               float* __restrict__ out, int B) {
    __shared__ float2 sU[DIM * 17];   // sU[col*17 + amp]
    __shared__ float4 sM[256];
    __shared__ float4 sT[81];

    const int t = threadIdx.x;
    const int lane = t & 31;
    const int wi = t >> 5;            // 4 warps
    const unsigned FULL = 0xffffffffu;

    // ---- Phase A: shuffle-circuit U builder (no __syncthreads inside) -----
    {
        float my_cy, my_sy, my_cz, my_sz;
        const float wy = (lane < 12) ? w[lane * 2 + 0] : 0.f;
        const float wz = (lane < 12) ? w[lane * 2 + 1] : 0.f;
        __sincosf(0.5f * wy, &my_sy, &my_cy);
        __sincosf(0.5f * wz, &my_sz, &my_cz);

        const int amp = lane & 15;
        // lane carries two column-pairs: pair p -> column wi*4 + 2p + (lane>>4)
        float re[2], im[2];
        int colp[2];
#pragma unroll
        for (int p = 0; p < 2; ++p) {
            colp[p] = (wi << 2) + (p << 1) + (lane >> 4);
            re[p] = (amp == colp[p]) ? 1.f : 0.f;
            im[p] = 0.f;
        }

#pragma unroll
        for (int layer = 0; layer < 3; ++layer) {
            {   // CNOT ring: new[amp] = old[Q(amp)] (gather within 16-lane half)
                const int srcLane = (lane & 16) | cnot_q(amp);
#pragma unroll
                for (int p = 0; p < 2; ++p) {
                    const float nre = __shfl_sync(FULL, re[p], srcLane);
                    const float nim = __shfl_sync(FULL, im[p], srcLane);
                    re[p] = nre; im[p] = nim;
                }
            }
#pragma unroll
            for (int g = 0; g < 4; ++g) {
                const int gidx = layer * 4 + g;
                const float cy = __shfl_sync(FULL, my_cy, gidx);
                const float sy = __shfl_sync(FULL, my_sy, gidx);
                const float cz = __shfl_sync(FULL, my_cz, gidx);
                const float sz = __shfl_sync(FULL, my_sz, gidx);
                const int bit = 3 - g, mask = 1 << bit;
#pragma unroll
                for (int p = 0; p < 2; ++p) {
                    const float pre = __shfl_xor_sync(FULL, re[p], mask);
                    const float pim = __shfl_xor_sync(FULL, im[p], mask);
                    float br, bi;
                    if (amp & mask) { br = sy * pre + cy * re[p]; bi = sy * pim + cy * im[p]; }
                    else            { br = cy * re[p] - sy * pre; bi = cy * im[p] - sy * pim; }
                    re[p] = br; im[p] = bi;
                    if (layer != 2) {   // RZ (last layer's RZ cancels in U^H S U)
                        if (amp & mask) { const float o = cz * br - sz * bi;
                                          im[p] = cz * bi + sz * br; re[p] = o; }
                        else            { const float o = cz * br + sz * bi;
                                          im[p] = cz * bi - sz * br; re[p] = o; }
                    }
                }
            }
        }
#pragma unroll
        for (int p = 0; p < 2; ++p)
            sU[colp[p] * 17 + amp] = make_float2(re[p], im[p]);
    }
    __syncthreads();

    // ---- Phase M: M_w[j,j'] = sum_k s_wk (Ur Ur' + Ui Ui') ----------------
#pragma unroll
    for (int e = t; e < 256; e += TPB) {
        const int j = e >> 4, jp = e & 15;
        float m0 = 0.f, m1 = 0.f, m2 = 0.f, m3 = 0.f;
#pragma unroll
        for (int k = 0; k < DIM; ++k) {
            const float2 a = sU[j * 17 + k];
            const float2 b = sU[jp * 17 + k];
            const float pr = a.x * b.x + a.y * b.y;
            if (k & 8) m0 -= pr; else m0 += pr;
            if (k & 4) m1 -= pr; else m1 += pr;
            if (k & 2) m2 -= pr; else m2 += pr;
            if (k & 1) m3 -= pr; else m3 += pr;
        }
        sM[e] = make_float4(m0, m1, m2, m3);
    }
    __syncthreads();

    // ---- Phase T: 81 monomial coefficients, straight into smem ------------
    if (t < 81) {
        const int i0 = t / 27, i1 = (t / 9) % 3, i2 = (t / 3) % 3, i3 = t % 3;
        const int M1 = ((i0 == 1) << 3) | ((i1 == 1) << 2) | ((i2 == 1) << 1) | (i3 == 1);
        const int M2 = ((i0 == 2) << 3) | ((i1 == 2) << 2) | ((i2 == 2) << 1) | (i3 == 2);
        float a0 = 0.f, a1 = 0.f, a2 = 0.f, a3 = 0.f;
#pragma unroll
        for (int b = 0; b < 16; ++b) {
            const float4 mm = sM[b * 16 + (b ^ M2)];
            const float sg = (__popc(b & M1) & 1) ? -1.f : 1.f;
            a0 += sg * mm.x; a1 += sg * mm.y; a2 += sg * mm.z; a3 += sg * mm.w;
        }
        const float s = 0.0625f;
        sT[t] = make_float4(a0 * s, a1 * s, a2 * s, a3 * s);
    }
    __syncthreads();

    // ---- Phase B: one tile per block, three-level Horner (R13-verified) ---
    const ulonglong2* cT = reinterpret_cast<const ulonglong2*>(sT);
    const int base = blockIdx.x * TILE + t;

    bool valid[EPT];
    unsigned long long c0d[EPT], s0d[EPT], c1d[EPT], s1d[EPT];
    unsigned long long c2d[EPT], s2d[EPT], c3d[EPT], s3d[EPT];
#pragma unroll
    for (int e = 0; e < EPT; ++e) {
        const int b = base + e * TPB;
        valid[e] = (b < B);
        const float4 xv = valid[e] ? reinterpret_cast<const float4*>(x)[b]
                                   : make_float4(0.f, 0.f, 0.f, 0.f);
        float c0, s0, c1, s1, c2, s2, c3, s3;
        __sincosf(xv.x, &s0, &c0);   // full angle (double-angle folded into T)
        __sincosf(xv.y, &s1, &c1);
        __sincosf(xv.z, &s2, &c2);
        __sincosf(xv.w, &s3, &c3);
        c0d[e] = pack2(c0, c0); s0d[e] = pack2(s0, s0);
        c1d[e] = pack2(c1, c1); s1d[e] = pack2(s1, s1);
        c2d[e] = pack2(c2, c2); s2d[e] = pack2(s2, s2);
        c3d[e] = pack2(c3, c3); s3d[e] = pack2(s3, s3);
    }

    unsigned long long z01[EPT], z23[EPT];
    unsigned long long Q01[EPT], Q23[EPT];

#pragma unroll
    for (int i0 = 0; i0 < 3; ++i0) {
#pragma unroll
        for (int i1 = 0; i1 < 3; ++i1) {
            const int gi = i0 * 3 + i1;
            ulonglong2 c[9];
#pragma unroll
            for (int k = 0; k < 9; ++k) c[k] = cT[gi * 9 + k];

#pragma unroll
            for (int e = 0; e < EPT; ++e) {
                const unsigned long long u0a =
                    fma2(c[2].x, s3d[e], fma2(c[1].x, c3d[e], c[0].x));
                const unsigned long long u1a =
                    fma2(c[5].x, s3d[e], fma2(c[4].x, c3d[e], c[3].x));
                const unsigned long long u2a =
                    fma2(c[8].x, s3d[e], fma2(c[7].x, c3d[e], c[6].x));
                const unsigned long long in01 =
                    fma2(u2a, s2d[e], fma2(u1a, c2d[e], u0a));
                const unsigned long long u0b =
                    fma2(c[2].y, s3d[e], fma2(c[1].y, c3d[e], c[0].y));
                const unsigned long long u1b =
                    fma2(c[5].y, s3d[e], fma2(c[4].y, c3d[e], c[3].y));
                const unsigned long long u2b =
                    fma2(c[8].y, s3d[e], fma2(c[7].y, c3d[e], c[6].y));
                const unsigned long long in23 =
                    fma2(u2b, s2d[e], fma2(u1b, c2d[e], u0b));

                if (i1 == 0)      { Q01[e] = in01;                       Q23[e] = in23; }
                else if (i1 == 1) { Q01[e] = fma2(c1d[e], in01, Q01[e]); Q23[e] = fma2(c1d[e], in23, Q23[e]); }
                else              { Q01[e] = fma2(s1d[e], in01, Q01[e]); Q23[e] = fma2(s1d[e], in23, Q23[e]); }
            }
        }
#pragma unroll
        for (int e = 0; e < EPT; ++e) {
            if (i0 == 0)      { z01[e] = Q01[e];                       z23[e] = Q23[e]; }
            else if (i0 == 1) { z01[e] = fma2(c0d[e], Q01[e], z01[e]); z23[e] = fma2(c0d[e], Q23[e], z23[e]); }
            else              { z01[e] = fma2(s0d[e], Q01[e], z01[e]); z23[e] = fma2(s0d[e], Q23[e], z23[e]); }
        }
    }

#pragma unroll
    for (int e = 0; e < EPT; ++e) {
        if (!valid[e]) continue;
        float z0, z1, z2, z3;
        unpack2(z01[e], z0, z1);
        unpack2(z23[e], z2, z3);
        reinterpret_cast<float4*>(out)[base + e * TPB] =
            make_float4(z0, z1, z2, z3);
    }
}

// ---------------------------------------------------------------------------
extern "C" void kernel_launch(void* const* d_in, const int* in_sizes, int n_in,
                              void* d_out, int out_size) {
    int ix = 0, iw = 1;
    if (n_in >= 2 && in_sizes[0] <= in_sizes[1]) { ix = 1; iw = 0; }
    const float* x = (const float*)d_in[ix];
    const float* w = (const float*)d_in[iw];
    float* out = (float*)d_out;
    const int B = in_sizes[ix] / 4;

    const int grid = (B + TILE - 1) / TILE;   // 2048 for B=524288
    vqc_fused<<<grid, TPB>>>(x, w, out, B);
}